// round 2
// baseline (speedup 1.0000x reference)
#include <cuda_runtime.h>
#include <cuda_bf16.h>
#include <cstdint>

// ============================================================================
// PhaseCoherenceComputer: C[bh,q,k] = mean_h cos(phq - phk)
//   = (cos_q @ cos_k^T + sin_q @ sin_k^T) / 64
// 16 GEMMs [2048,128]@[128,2048]^T, fp32 accuracy via 2-term bf16 split:
//   x = hi + lo;  C = Ah@Bh + Ah@Bl + Al@Bh   (lo@lo ~ 2^-18, dropped)
// Implemented as 6 K=64 segments over scratch layout [row][256]:
//   cols 0-63 cos_hi | 64-127 sin_hi | 128-191 cos_lo | 192-255 sin_lo
// mma.sync (HMMA) path only — tcgen05 is arch-conditional (sm_103a) and the
// harness compiles via compute_103, so 'a'-features are unavailable.
// ============================================================================

#define NBH 16
#define SEQ 2048
#define NH  64
#define KS  256          // scratch K width (hi 128 | lo 128)
#define BM  128
#define BN  128
#define BK  64
#define STAGES 3
#define KITERS 6         // 3 products x (128/64)

// ---------------- scratch (device globals; no allocation APIs) --------------
__device__ __align__(16) __nv_bfloat16 gA[NBH * SEQ * KS];   // 16 MB
__device__ __align__(16) __nv_bfloat16 gB[NBH * SEQ * KS];   // 16 MB

__device__ __forceinline__ uint32_t smem_u32(const void* p) {
    uint32_t a;
    asm("{ .reg .u64 t; cvta.to.shared.u64 t, %1; cvt.u32.u64 %0, t; }"
        : "=r"(a) : "l"(p));
    return a;
}

#define CP_ASYNC_16(smem, gptr)                                                \
    asm volatile("cp.async.cg.shared.global [%0], [%1], 16;"                   \
                 :: "r"(smem), "l"(gptr))
#define CP_COMMIT()  asm volatile("cp.async.commit_group;" ::: "memory")
#define CP_WAIT(N)   asm volatile("cp.async.wait_group %0;" :: "n"(N) : "memory")

#define LDSM_X4(r0, r1, r2, r3, addr)                                          \
    asm volatile("ldmatrix.sync.aligned.m8n8.x4.shared.b16 {%0,%1,%2,%3}, [%4];" \
                 : "=r"(r0), "=r"(r1), "=r"(r2), "=r"(r3) : "r"(addr))

#define MMA_BF16(c0, c1, c2, c3, a0, a1, a2, a3, b0, b1)                       \
    asm volatile("mma.sync.aligned.m16n8k16.row.col.f32.bf16.bf16.f32 "        \
                 "{%0,%1,%2,%3}, {%4,%5,%6,%7}, {%8,%9}, {%0,%1,%2,%3};"       \
                 : "+f"(c0), "+f"(c1), "+f"(c2), "+f"(c3)                      \
                 : "r"(a0), "r"(a1), "r"(a2), "r"(a3), "r"(b0), "r"(b1))

// ============================================================================
// Kernel 1: sincos + bf16 hi/lo split
// ============================================================================
__global__ void phase_prep_kernel(const float* __restrict__ q,
                                  const float* __restrict__ k)
{
    const int NPER = NBH * SEQ * NH;   // 2,097,152 per tensor
    int idx = blockIdx.x * blockDim.x + threadIdx.x;
    if (idx >= 2 * NPER) return;
    bool isQ = idx < NPER;
    int li = isQ ? idx : idx - NPER;
    float x = isQ ? q[li] : k[li];

    int row = li >> 6;
    int h   = li & 63;

    float s, c;
    sincosf(x, &s, &c);
    __nv_bfloat16 ch = __float2bfloat16(c);
    __nv_bfloat16 cl = __float2bfloat16(c - __bfloat162float(ch));
    __nv_bfloat16 sh = __float2bfloat16(s);
    __nv_bfloat16 sl = __float2bfloat16(s - __bfloat162float(sh));

    __nv_bfloat16* dst = (isQ ? gA : gB) + (size_t)row * KS;
    dst[h]       = ch;
    dst[h + 64]  = sh;
    dst[h + 128] = cl;
    dst[h + 192] = sl;
}

// ============================================================================
// Kernel 2: bf16 mma.sync GEMM, BM=BN=128, BK=64, 3-stage cp.async pipeline
// grid = (16 ntiles, 16 mtiles, 16 bh), 256 threads (2x4 warps, 64x32 tiles)
// ============================================================================
// smem per stage: A 128x64 bf16 (16 KB, 128B rows) + B same. XOR-8 swizzle.
#define STG_BYTES (2 * BM * BK * 2)           // 32768
#define SMEM_TOTAL (STAGES * STG_BYTES)       // 98304

// K-segment offsets (elements) inside the [row][256] scratch per k-iteration:
// products: (Ah,Bh) (Ah,Bl) (Al,Bh), each split into two K=64 halves.
__device__ __constant__ int kAOff[KITERS] = {0, 64, 0,   64,  128, 192};
__device__ __constant__ int kBOff[KITERS] = {0, 64, 128, 192, 0,   64};

__global__ void __launch_bounds__(256, 2)
phase_gemm_kernel(float* __restrict__ out)
{
    extern __shared__ char smem[];
    const uint32_t sb = smem_u32(smem);
    const int tid  = threadIdx.x;
    const int wid  = tid >> 5;
    const int lane = tid & 31;
    const int wm   = wid >> 2;          // 0-1
    const int wn   = wid & 3;           // 0-3

    const int nt = blockIdx.x;
    const int mt = blockIdx.y;
    const int bh = blockIdx.z;

    const __nv_bfloat16* __restrict__ pA =
        gA + ((size_t)bh * SEQ + (size_t)mt * BM) * KS;
    const __nv_bfloat16* __restrict__ pB =
        gB + ((size_t)bh * SEQ + (size_t)nt * BN) * KS;

    // per-thread gmem->smem mapping: 4 chunks of 16B per tile per stage
    const int ldRow = tid >> 3;          // 0-31 base row (x4 via +32 stride? no:)
    // chunkId = tid + t*256, t in 0..3 -> row = chunkId/8 (0..127), chunk = chunkId%8
    const int ldChk = tid & 7;

    // smem store offsets (swizzled), same for A and B tiles
    uint32_t stSm[4];
    size_t   stGm[4];
#pragma unroll
    for (int t = 0; t < 4; t++) {
        int row = ldRow + t * 32;
        int chk = ldChk;
        stSm[t] = (uint32_t)(row * 128 + ((chk ^ (row & 7)) << 4));
        stGm[t] = (size_t)row * KS + chk * 8;   // elements; +segOff later
    }

    // ldmatrix base rows
    const int rl  = lane & 15;
    const int hc  = lane >> 4;           // 0/1 -> +8 in k
    uint32_t aRow[4], bRow[2];
#pragma unroll
    for (int mf = 0; mf < 4; mf++) aRow[mf] = (uint32_t)(wm * 64 + mf * 16 + rl);
#pragma unroll
    for (int p = 0; p < 2; p++)   bRow[p]  = (uint32_t)(wn * 32 + p * 16 + rl);

    float acc[4][4][4];
#pragma unroll
    for (int mf = 0; mf < 4; mf++)
#pragma unroll
        for (int nf = 0; nf < 4; nf++)
#pragma unroll
            for (int j = 0; j < 4; j++) acc[mf][nf][j] = 0.0f;

    // ---- issue prologue stages ----
#pragma unroll
    for (int s = 0; s < STAGES - 1; s++) {
        uint32_t base = sb + s * STG_BYTES;
        int ao = kAOff[s], bo = kBOff[s];
#pragma unroll
        for (int t = 0; t < 4; t++) {
            CP_ASYNC_16(base + stSm[t],                 pA + stGm[t] + ao);
            CP_ASYNC_16(base + (BM * BK * 2) + stSm[t], pB + stGm[t] + bo);
        }
        CP_COMMIT();
    }

    for (int ki = 0; ki < KITERS; ki++) {
        CP_WAIT(STAGES - 2);
        __syncthreads();

        // issue next stage (buffer (ki-1)%S is free: all warps synced)
        {
            int nk = ki + STAGES - 1;
            if (nk < KITERS) {
                uint32_t base = sb + (nk % STAGES) * STG_BYTES;
                int ao = kAOff[nk], bo = kBOff[nk];
#pragma unroll
                for (int t = 0; t < 4; t++) {
                    CP_ASYNC_16(base + stSm[t],                 pA + stGm[t] + ao);
                    CP_ASYNC_16(base + (BM * BK * 2) + stSm[t], pB + stGm[t] + bo);
                }
            }
            CP_COMMIT();   // empty group at tail keeps wait_group counting aligned
        }

        // compute on stage ki%S
        const uint32_t aBase = sb + (ki % STAGES) * STG_BYTES;
        const uint32_t bBase = aBase + BM * BK * 2;
#pragma unroll
        for (int kk = 0; kk < 4; kk++) {
            const int kk2 = kk * 2;
            uint32_t a[4][4];
#pragma unroll
            for (int mf = 0; mf < 4; mf++) {
                uint32_t r = aRow[mf];
                uint32_t addr = aBase + r * 128 + ((((uint32_t)(kk2 + hc)) ^ (r & 7)) << 4);
                LDSM_X4(a[mf][0], a[mf][1], a[mf][2], a[mf][3], addr);
            }
            uint32_t b[4][2];   // [nfrag][2]
#pragma unroll
            for (int p = 0; p < 2; p++) {
                uint32_t r = bRow[p];
                uint32_t addr = bBase + r * 128 + ((((uint32_t)(kk2 + hc)) ^ (r & 7)) << 4);
                uint32_t r0, r1, r2, r3;
                LDSM_X4(r0, r1, r2, r3, addr);
                b[p * 2][0]     = r0; b[p * 2][1]     = r2;
                b[p * 2 + 1][0] = r1; b[p * 2 + 1][1] = r3;
            }
#pragma unroll
            for (int mf = 0; mf < 4; mf++)
#pragma unroll
                for (int nf = 0; nf < 4; nf++)
                    MMA_BF16(acc[mf][nf][0], acc[mf][nf][1],
                             acc[mf][nf][2], acc[mf][nf][3],
                             a[mf][0], a[mf][1], a[mf][2], a[mf][3],
                             b[nf][0], b[nf][1]);
        }
        __syncthreads();
    }

    // ---- epilogue: scale 1/64, store fp32 ----
    const float scale = 1.0f / (float)NH;
    const int qg = lane >> 2;            // 0-7 row group
    const int cp2 = (lane & 3) * 2;      // col pair
    float* obase = out + ((size_t)bh * SEQ + (size_t)mt * BM + wm * 64) * SEQ
                       + (size_t)nt * BN + wn * 32;
#pragma unroll
    for (int mf = 0; mf < 4; mf++) {
#pragma unroll
        for (int nf = 0; nf < 4; nf++) {
            float* p0 = obase + (size_t)(mf * 16 + qg) * SEQ + nf * 8 + cp2;
            float2 v0 = make_float2(acc[mf][nf][0] * scale, acc[mf][nf][1] * scale);
            float2 v1 = make_float2(acc[mf][nf][2] * scale, acc[mf][nf][3] * scale);
            *(float2*)p0            = v0;
            *(float2*)(p0 + 8 * SEQ) = v1;
        }
    }
}

// ============================================================================
// launch
// ============================================================================
extern "C" void kernel_launch(void* const* d_in, const int* in_sizes, int n_in,
                              void* d_out, int out_size)
{
    const float* q = (const float*)d_in[0];
    const float* k = (const float*)d_in[1];
    float* out = (float*)d_out;

    cudaFuncSetAttribute(phase_gemm_kernel,
                         cudaFuncAttributeMaxDynamicSharedMemorySize, SMEM_TOTAL);

    const int NPER = NBH * SEQ * NH;
    int threads = 256;
    int blocks = (2 * NPER + threads - 1) / threads;
    phase_prep_kernel<<<blocks, threads>>>(q, k);

    dim3 grid(SEQ / BN, SEQ / BM, NBH);   // (16,16,16)
    phase_gemm_kernel<<<grid, 256, SMEM_TOTAL>>>(out);
}

// round 3
// speedup vs baseline: 2.1812x; 2.1812x over previous
#include <cuda_runtime.h>
#include <cuda_fp16.h>
#include <cstdint>

// ============================================================================
// PhaseCoherenceComputer: C[bh,q,k] = mean_h cos(phq - phk)
//   = (cos_q @ cos_k^T + sin_q @ sin_k^T) / 64
// 16 GEMMs [2048,128]@[128,2048]^T in fp16 (single product — fp16's 10-bit
// mantissa gives ~1.5e-4 norm rel-err over K=128, 7x under the 1e-3 bar).
// The 1/64 mean-scale is folded into the A scratch at prep time.
// Scratch layout per row (K=128 fp16): cols 0-63 cos | 64-127 sin.
// mma.sync (HMMA) path — tcgen05 is sm_103a-gated and the harness targets
// compute_103 (no 'a'), so 'a'-features are unavailable.
// ============================================================================

#define NBH 16
#define SEQ 2048
#define NH  64
#define KS  128          // scratch K width (cos 64 | sin 64)
#define BM  128
#define BN  128
#define BK  64
#define KITERS 2

// ---------------- scratch (device globals; no allocation APIs) --------------
__device__ __align__(16) __half gA[NBH * SEQ * KS];   // 8 MB (pre-scaled 1/64)
__device__ __align__(16) __half gB[NBH * SEQ * KS];   // 8 MB

__device__ __forceinline__ uint32_t smem_u32(const void* p) {
    uint32_t a;
    asm("{ .reg .u64 t; cvta.to.shared.u64 t, %1; cvt.u32.u64 %0, t; }"
        : "=r"(a) : "l"(p));
    return a;
}

#define CP_ASYNC_16(smem, gptr)                                                \
    asm volatile("cp.async.cg.shared.global [%0], [%1], 16;"                   \
                 :: "r"(smem), "l"(gptr))
#define CP_COMMIT()  asm volatile("cp.async.commit_group;" ::: "memory")
#define CP_WAIT(N)   asm volatile("cp.async.wait_group %0;" :: "n"(N) : "memory")

#define LDSM_X4(r0, r1, r2, r3, addr)                                          \
    asm volatile("ldmatrix.sync.aligned.m8n8.x4.shared.b16 {%0,%1,%2,%3}, [%4];" \
                 : "=r"(r0), "=r"(r1), "=r"(r2), "=r"(r3) : "r"(addr))

#define MMA_F16(c0, c1, c2, c3, a0, a1, a2, a3, b0, b1)                        \
    asm volatile("mma.sync.aligned.m16n8k16.row.col.f32.f16.f16.f32 "          \
                 "{%0,%1,%2,%3}, {%4,%5,%6,%7}, {%8,%9}, {%0,%1,%2,%3};"       \
                 : "+f"(c0), "+f"(c1), "+f"(c2), "+f"(c3)                      \
                 : "r"(a0), "r"(a1), "r"(a2), "r"(a3), "r"(b0), "r"(b1))

// ============================================================================
// Kernel 1: sincos -> fp16 scratch. One thread = 4 harmonics (float4 load,
// two 8B half stores). A side pre-scaled by 1/NH.
// ============================================================================
__global__ void phase_prep_kernel(const float* __restrict__ q,
                                  const float* __restrict__ k)
{
    const int NT = NBH * SEQ * (NH / 4);    // 524288 threads per tensor
    int idx = blockIdx.x * blockDim.x + threadIdx.x;
    if (idx >= 2 * NT) return;
    bool isQ = idx < NT;
    int li  = isQ ? idx : idx - NT;
    int row = li >> 4;
    int h4  = (li & 15) << 2;

    const float4 v = *(const float4*)((isQ ? q : k) + (size_t)row * NH + h4);
    const float sc = isQ ? (1.0f / (float)NH) : 1.0f;

    float s0, c0, s1, c1, s2, c2, s3, c3;
    sincosf(v.x, &s0, &c0);
    sincosf(v.y, &s1, &c1);
    sincosf(v.z, &s2, &c2);
    sincosf(v.w, &s3, &c3);

    __half2 ca = __floats2half2_rn(c0 * sc, c1 * sc);
    __half2 cb = __floats2half2_rn(c2 * sc, c3 * sc);
    __half2 sa = __floats2half2_rn(s0 * sc, s1 * sc);
    __half2 sb = __floats2half2_rn(s2 * sc, s3 * sc);

    __half* dst = (isQ ? gA : gB) + (size_t)row * KS;
    uint2 uc, us;
    uc.x = *reinterpret_cast<uint32_t*>(&ca);
    uc.y = *reinterpret_cast<uint32_t*>(&cb);
    us.x = *reinterpret_cast<uint32_t*>(&sa);
    us.y = *reinterpret_cast<uint32_t*>(&sb);
    *(uint2*)(dst + h4)      = uc;
    *(uint2*)(dst + 64 + h4) = us;
}

// ============================================================================
// Kernel 2: fp16 mma.sync GEMM, BM=BN=128, BK=64, 2 K-iters (both stages
// issued up-front). grid = (16,16,16), 256 threads (2x4 warps, 64x32 tiles).
// ============================================================================
#define STG_BYTES (2 * BM * BK * 2)           // 32768 (A tile + B tile)
#define SMEM_TOTAL (KITERS * STG_BYTES)       // 65536

__global__ void __launch_bounds__(256, 2)
phase_gemm_kernel(float* __restrict__ out)
{
    extern __shared__ char smem[];
    const uint32_t sb = smem_u32(smem);
    const int tid  = threadIdx.x;
    const int wid  = tid >> 5;
    const int lane = tid & 31;
    const int wm   = wid >> 2;          // 0-1
    const int wn   = wid & 3;           // 0-3

    const int nt = blockIdx.x;
    const int mt = blockIdx.y;
    const int bh = blockIdx.z;

    const __half* __restrict__ pA = gA + ((size_t)bh * SEQ + (size_t)mt * BM) * KS;
    const __half* __restrict__ pB = gB + ((size_t)bh * SEQ + (size_t)nt * BN) * KS;

    const int ldRow = tid >> 3;          // base row, +32 stride x4
    const int ldChk = tid & 7;           // 16B chunk in 128B smem row

    uint32_t stSm[4];
    size_t   stGm[4];
#pragma unroll
    for (int t = 0; t < 4; t++) {
        int row = ldRow + t * 32;
        stSm[t] = (uint32_t)(row * 128 + ((ldChk ^ (row & 7)) << 4));
        stGm[t] = (size_t)row * KS + ldChk * 8;
    }

    // ---- issue both K stages up front ----
#pragma unroll
    for (int s = 0; s < KITERS; s++) {
        uint32_t base = sb + s * STG_BYTES;
        const int off = s * BK;
#pragma unroll
        for (int t = 0; t < 4; t++) {
            CP_ASYNC_16(base + stSm[t],                 pA + stGm[t] + off);
            CP_ASYNC_16(base + (BM * BK * 2) + stSm[t], pB + stGm[t] + off);
        }
        CP_COMMIT();
    }

    // ldmatrix base rows
    const int rl = lane & 15;
    const int hc = lane >> 4;
    uint32_t aRow[4], bRow[2];
#pragma unroll
    for (int mf = 0; mf < 4; mf++) aRow[mf] = (uint32_t)(wm * 64 + mf * 16 + rl);
#pragma unroll
    for (int p = 0; p < 2; p++)   bRow[p]  = (uint32_t)(wn * 32 + p * 16 + rl);

    float acc[4][4][4];
#pragma unroll
    for (int mf = 0; mf < 4; mf++)
#pragma unroll
        for (int nf = 0; nf < 4; nf++)
#pragma unroll
            for (int j = 0; j < 4; j++) acc[mf][nf][j] = 0.0f;

#pragma unroll
    for (int ki = 0; ki < KITERS; ki++) {
        if (ki == 0) { CP_WAIT(1); } else { CP_WAIT(0); }
        __syncthreads();

        const uint32_t aBase = sb + ki * STG_BYTES;
        const uint32_t bBase = aBase + BM * BK * 2;
#pragma unroll
        for (int kk = 0; kk < 4; kk++) {
            const int kk2 = kk * 2;
            uint32_t a[4][4];
#pragma unroll
            for (int mf = 0; mf < 4; mf++) {
                uint32_t r = aRow[mf];
                uint32_t addr = aBase + r * 128 + ((((uint32_t)(kk2 + hc)) ^ (r & 7)) << 4);
                LDSM_X4(a[mf][0], a[mf][1], a[mf][2], a[mf][3], addr);
            }
            uint32_t b[4][2];
#pragma unroll
            for (int p = 0; p < 2; p++) {
                uint32_t r = bRow[p];
                uint32_t addr = bBase + r * 128 + ((((uint32_t)(kk2 + hc)) ^ (r & 7)) << 4);
                uint32_t r0, r1, r2, r3;
                LDSM_X4(r0, r1, r2, r3, addr);
                b[p * 2][0]     = r0; b[p * 2][1]     = r2;
                b[p * 2 + 1][0] = r1; b[p * 2 + 1][1] = r3;
            }
#pragma unroll
            for (int mf = 0; mf < 4; mf++)
#pragma unroll
                for (int nf = 0; nf < 4; nf++)
                    MMA_F16(acc[mf][nf][0], acc[mf][nf][1],
                            acc[mf][nf][2], acc[mf][nf][3],
                            a[mf][0], a[mf][1], a[mf][2], a[mf][3],
                            b[nf][0], b[nf][1]);
        }
    }

    // ---- epilogue: direct fp32 stores (scale pre-folded into A) ----
    const int qg  = lane >> 2;
    const int cp2 = (lane & 3) * 2;
    float* obase = out + ((size_t)bh * SEQ + (size_t)mt * BM + wm * 64) * SEQ
                       + (size_t)nt * BN + wn * 32;
#pragma unroll
    for (int mf = 0; mf < 4; mf++) {
#pragma unroll
        for (int nf = 0; nf < 4; nf++) {
            float* p0 = obase + (size_t)(mf * 16 + qg) * SEQ + nf * 8 + cp2;
            *(float2*)p0             = make_float2(acc[mf][nf][0], acc[mf][nf][1]);
            *(float2*)(p0 + 8 * SEQ) = make_float2(acc[mf][nf][2], acc[mf][nf][3]);
        }
    }
}

// ============================================================================
// launch
// ============================================================================
extern "C" void kernel_launch(void* const* d_in, const int* in_sizes, int n_in,
                              void* d_out, int out_size)
{
    const float* q = (const float*)d_in[0];
    const float* k = (const float*)d_in[1];
    float* out = (float*)d_out;

    cudaFuncSetAttribute(phase_gemm_kernel,
                         cudaFuncAttributeMaxDynamicSharedMemorySize, SMEM_TOTAL);

    const int NT = NBH * SEQ * (NH / 4);
    int threads = 256;
    int blocks = (2 * NT + threads - 1) / threads;
    phase_prep_kernel<<<blocks, threads>>>(q, k);

    dim3 grid(SEQ / BN, SEQ / BM, NBH);   // (16,16,16)
    phase_gemm_kernel<<<grid, 256, SMEM_TOTAL>>>(out);
}